// round 5
// baseline (speedup 1.0000x reference)
#include <cuda_runtime.h>
#include <math.h>

// Shapes fixed by the problem: T=3, B=4, N=4096, K=8.
constexpr int TT = 3;
constexpr int BB = 4;
constexpr int NN = 4096;
constexpr int KK = 8;
constexpr int CHUNKS = 4;
constexpr int CHUNK_COLS = NN / CHUNKS;   // 1024

// Partial-sum slot layout (deterministic reduction — no float atomics)
constexpr int P_CH   = 0;                  // 24 problems * 16 blocks = 384
constexpr int P_PD   = 384;                // 64
constexpr int P_SP   = 448;                // 64
constexpr int P_TRAN = 512;                // 1
constexpr int P_ARAP = 513;                // 3 * 64 = 192
constexpr int NPART  = 705;

// Scratch (device globals — no allocations allowed)
__device__ float4 g_cols_src[BB * NN];         // (-2x, -2y, -2z, |x|^2) of source
__device__ float4 g_cols_tgt[BB * NN];         // same for target
__device__ float4 g_cols_dp[TT * BB * NN];     // same for deformation points per t
__device__ float  g_nb_d[BB * NN * CHUNKS * KK];
__device__ int    g_nb_i[BB * NN * CHUNKS * KK];
__device__ int    g_idx[BB * NN * KK];
__device__ float  g_sd[BB * NN * KK];
__device__ float  g_partial[NPART];

// ---------------------------------------------------------------------------
__device__ __forceinline__ float block_reduce_sum(float v, float* sh) {
    int tid = threadIdx.x;             // blockDim.x == 256 assumed
    sh[tid] = v;
    __syncthreads();
    #pragma unroll
    for (int s = 128; s > 0; s >>= 1) {
        if (tid < s) sh[tid] += sh[tid + s];
        __syncthreads();
    }
    float r = sh[0];
    __syncthreads();
    return r;
}

__device__ __forceinline__ void insert8(float d, int n, float (&bd)[KK], int (&bi)[KK]) {
    float cd = d; int ci = n;
    #pragma unroll
    for (int s = 0; s < KK; ++s) {
        if (cd < bd[s]) {
            float td = bd[s]; int ti = bi[s];
            bd[s] = cd; bi[s] = ci;
            cd = td; ci = ti;
        }
    }
}

// ---------------------------------------------------------------------------
// Build transformed column arrays: (-2p, |p|^2) for source, target, dp[t].
__global__ void prep_kernel(const float* __restrict__ src,
                            const float* __restrict__ tgt,
                            const float* __restrict__ dpt) {
    int i = blockIdx.x * 256 + threadIdx.x;            // over (2+TT)*BB*NN
    const float* p;
    float4* o;
    if (i < BB * NN)              { p = src + 3 * i;                o = g_cols_src + i; }
    else if (i < 2 * BB * NN)     { int j = i - BB * NN;  p = tgt + 3 * j; o = g_cols_tgt + j; }
    else {
        int j = i - 2 * BB * NN;
        if (j >= TT * BB * NN) return;
        p = dpt + 3 * j; o = g_cols_dp + j;
    }
    float x = p[0], y = p[1], z = p[2];
    *o = make_float4(-2.0f * x, -2.0f * y, -2.0f * z,
                     fmaf(x, x, fmaf(y, y, z * z)));
}

// ---------------------------------------------------------------------------
// pd (sum sq diff), sp (sum abs), tran (tiny) — partial sums per block.
__global__ void small_kernel(const float* __restrict__ pw,
                             const float* __restrict__ drp,
                             const float* __restrict__ dpt,
                             const float* __restrict__ rig) {
    __shared__ float red[256];
    int g = blockIdx.x * 256 + threadIdx.x;
    float spa = 0.f, pda = 0.f;
    for (int i = g; i < TT * BB * NN; i += 64 * 256) {
        spa += fabsf(pw[i]);
        int b3 = i * 3;
        float a = drp[b3 + 0] - dpt[b3 + 0];
        float c = drp[b3 + 1] - dpt[b3 + 1];
        float e = drp[b3 + 2] - dpt[b3 + 2];
        pda += fmaf(a, a, fmaf(c, c, e * e));
    }
    float s1 = block_reduce_sum(pda, red);
    if (threadIdx.x == 0) g_partial[P_PD + blockIdx.x] = s1;
    float s2 = block_reduce_sum(spa, red);
    if (threadIdx.x == 0) g_partial[P_SP + blockIdx.x] = s2;

    float ta = 0.f;
    if (blockIdx.x == 0 && threadIdx.x < TT * BB * 3) {
        int t = threadIdx.x / 12;
        int rem = threadIdx.x % 12;
        int b = rem / 3, r = rem % 3;
        float v = rig[(((t * BB + b) * 4) + r) * 4 + 3];
        ta = v * v;
    }
    float s3 = block_reduce_sum(ta, red);
    if (blockIdx.x == 0 && threadIdx.x == 0) g_partial[P_TRAN] = s3;
}

// ---------------------------------------------------------------------------
// kNN over source points, split into CHUNKS column chunks for occupancy.
// Each thread owns one row, keeps a sorted top-8 of *relative* distances
// (d_rel = |y|^2 - 2 x.y; per-row constant |x|^2 dropped — order preserved).
__global__ void nb_kernel(const float* __restrict__ src) {
    __shared__ float4 tile[CHUNK_COLS];
    int tid = threadIdx.x;
    int m = blockIdx.x * 256 + tid;          // 0 .. B*N-1
    int b = m >> 12;
    int ml = m & (NN - 1);
    int chunk = blockIdx.y;

    const float4* cb = g_cols_src + b * NN + chunk * CHUNK_COLS;
    for (int j = tid; j < CHUNK_COLS; j += 256) tile[j] = cb[j];
    __syncthreads();

    const float* rp = src + (size_t)m * 3;
    float x0 = rp[0], x1 = rp[1], x2 = rp[2];

    float bd[KK]; int bi[KK];
    #pragma unroll
    for (int k = 0; k < KK; ++k) { bd[k] = 3.4e38f; bi[k] = 0; }

    int nbase = chunk * CHUNK_COLS;
    #pragma unroll 4
    for (int j = 0; j < CHUNK_COLS; ++j) {
        float4 q = tile[j];
        float d = fmaf(x2, q.z, fmaf(x1, q.y, fmaf(x0, q.x, q.w)));
        int n = nbase + j;
        if (d < bd[KK - 1] && n != ml) insert8(d, n, bd, bi);
    }

    int base = (m * CHUNKS + chunk) * KK;
    #pragma unroll
    for (int k = 0; k < KK; ++k) { g_nb_d[base + k] = bd[k]; g_nb_i[base + k] = bi[k]; }
}

// Merge per-chunk top-8 lists into final top-8; emit idx + sqrt(sd^2 + 1e-5).
__global__ void nb_merge_kernel(const float* __restrict__ src) {
    int m = blockIdx.x * 256 + threadIdx.x;
    float bd[KK]; int bi[KK];
    #pragma unroll
    for (int k = 0; k < KK; ++k) { bd[k] = 3.4e38f; bi[k] = 0; }
    int base = m * CHUNKS * KK;
    for (int c = 0; c < CHUNKS * KK; ++c) {
        float d = g_nb_d[base + c];
        if (d < bd[KK - 1]) insert8(d, g_nb_i[base + c], bd, bi);
    }
    const float* rp = src + (size_t)m * 3;
    float x0 = rp[0], x1 = rp[1], x2 = rp[2];
    float x2m = fmaf(x0, x0, fmaf(x1, x1, x2 * x2));
    #pragma unroll
    for (int k = 0; k < KK; ++k) {
        g_idx[m * KK + k] = bi[k];
        g_sd[m * KK + k]  = sqrtf(bd[k] + x2m + 1e-5f);
    }
}

// ---------------------------------------------------------------------------
// Chamfer: 24 problems = (t, b, dir). dir0: rows=dp, cols=target.
// dir1: rows=target, cols=dp. Each thread owns one row; inner loop is
// 1 LDS.128 (warp-broadcast) + 3 FFMA + 1 FMNMX per pair.
__global__ void chamfer_kernel(const float* __restrict__ dpt,
                               const float* __restrict__ tgt) {
    __shared__ float4 tile[1024];
    __shared__ float red[256];
    int tid = threadIdx.x;
    int p = blockIdx.y;               // p = ((t*BB + b)*2 + dir)
    int dir = p & 1;
    int tb = p >> 1;                  // t*BB + b
    int b = tb & 3;

    const float* rowp;
    const float4* colp;
    if (dir == 0) { rowp = dpt + (size_t)tb * NN * 3; colp = g_cols_tgt + b * NN; }
    else          { rowp = tgt + (size_t)b * NN * 3;  colp = g_cols_dp + (size_t)tb * NN; }

    int m = blockIdx.x * 256 + tid;
    const float* rp = rowp + (size_t)m * 3;
    float x0 = rp[0], x1 = rp[1], x2 = rp[2];
    float x2m = fmaf(x0, x0, fmaf(x1, x1, x2 * x2));

    float rmin = 3.4e38f;
    for (int t0 = 0; t0 < NN; t0 += 1024) {
        __syncthreads();
        for (int j = tid; j < 1024; j += 256) tile[j] = colp[t0 + j];
        __syncthreads();
        #pragma unroll 8
        for (int j = 0; j < 1024; ++j) {
            float4 q = tile[j];
            float d = fmaf(x2, q.z, fmaf(x1, q.y, fmaf(x0, q.x, q.w)));
            rmin = fminf(rmin, d);
        }
    }
    float v = rmin + x2m;
    float s = block_reduce_sum(v, red);
    if (tid == 0) g_partial[P_CH + p * 16 + blockIdx.x] = s;
}

// ---------------------------------------------------------------------------
// ARAP per t: gather dp neighbors by precomputed idx, compare to source dists.
__global__ void arap_kernel(const float* __restrict__ dpt) {
    __shared__ float red[256];
    int t = blockIdx.y;
    int i = blockIdx.x * 256 + threadIdx.x;    // b*NN + n
    int b = i >> 12;
    int n = i & (NN - 1);
    const float* dpb = dpt + ((size_t)(t * BB + b)) * NN * 3;
    float px = dpb[n * 3 + 0], py = dpb[n * 3 + 1], pz = dpb[n * 3 + 2];
    float acc = 0.f;
    #pragma unroll
    for (int k = 0; k < KK; ++k) {
        int j = g_idx[i * KK + k];
        float dx = dpb[j * 3 + 0] - px;
        float dy = dpb[j * 3 + 1] - py;
        float dz = dpb[j * 3 + 2] - pz;
        float dd = sqrtf(fmaf(dx, dx, fmaf(dy, dy, dz * dz)) + 1e-5f);
        float df = dd - g_sd[i * KK + k];
        acc = fmaf(df, df, acc);
    }
    float s = block_reduce_sum(acc, red);
    if (threadIdx.x == 0) g_partial[P_ARAP + t * 64 + blockIdx.x] = s;
}

// ---------------------------------------------------------------------------
// Final deterministic weighted reduction of all partial slots.
__global__ void final_kernel(float* __restrict__ out) {
    __shared__ float red[256];
    int tid = threadIdx.x;
    float acc = 0.f;
    for (int s = tid; s < NPART; s += 256) {
        float w;
        if (s < P_PD)        w = 0.5f / BB;          // chamfer: *0.5/B
        else if (s < P_SP)   w = 1.0f / BB;          // pd: /B
        else if (s < P_TRAN) w = 1.0f / (BB * NN);   // sp: mean over B*N
        else                 w = 1.0f / BB;          // tran + arap: /B
        acc += w * g_partial[s];
    }
    float s = block_reduce_sum(acc, red);
    if (tid == 0) out[0] = s;
}

// ---------------------------------------------------------------------------
extern "C" void kernel_launch(void* const* d_in, const int* in_sizes, int n_in,
                              void* d_out, int out_size) {
    (void)in_sizes; (void)n_in; (void)out_size;
    const float* pw  = (const float*)d_in[1];  // point_weight [T,B,N,1]
    const float* drp = (const float*)d_in[2];  // deform_rigid_points [T,B,N,3]
    const float* dpt = (const float*)d_in[3];  // deformation_points [T,B,N,3]
    const float* rig = (const float*)d_in[4];  // rigid_matrix [T,B,4,4]
    const float* src = (const float*)d_in[5];  // source_points [B,N,3]
    const float* tgt = (const float*)d_in[6];  // target_points [B,N,3]

    prep_kernel<<<(2 + TT) * BB * NN / 256, 256>>>(src, tgt, dpt);
    small_kernel<<<64, 256>>>(pw, drp, dpt, rig);
    nb_kernel<<<dim3(BB * NN / 256, CHUNKS), 256>>>(src);
    nb_merge_kernel<<<BB * NN / 256, 256>>>(src);
    chamfer_kernel<<<dim3(16, 24), 256>>>(dpt, tgt);
    arap_kernel<<<dim3(BB * NN / 256, TT), 256>>>(dpt);
    final_kernel<<<1, 256>>>((float*)d_out);
}